// round 7
// baseline (speedup 1.0000x reference)
#include <cuda_runtime.h>

#define NN 8192
#define MM 2048
#define DD 256
#define DHH 8
#define ROW_CAP 64
#define COL_CAP 128
#define PROJ_BLOCKS 40          // (NN+MM)/256
#define SCAN_BLOCKS 2048
#define SCAN_ITERS 8            // NN*MM/4 / (SCAN_BLOCKS*256)

// ---------------- scratch (static device globals; zero-init at load) ---------
__device__ float g_sx[NN];
__device__ float g_s2[NN];
__device__ float g_se[MM];
__device__ float g_s1[MM];
__device__ int   g_row_cnt[NN];        // zero at entry; re-zeroed in k_out
__device__ int   g_col_cnt[MM];
__device__ __align__(16) int g_row_edges[NN * ROW_CAP];
__device__ int   g_col_nodes[MM * COL_CAP];
// packed per-node record: [sx, rowSum(atomic), s2, 0, WX0..7, pad4] (stride 16)
__device__ __align__(16) float g_npack[NN * 16];
__device__ float g_colsum[MM];                      // zero at entry; re-zeroed in k_out
__device__ __align__(16) float g_empty_wx[DHH];     // zeroed by proj each replay
__device__ __align__(16) float g_empty_en[DHH];
__device__ float g_xacc[NN * DHH];                  // zero at entry; re-zeroed in k_out
__device__ int   g_proj_done;                       // reset by k_out

__device__ __forceinline__ float leaky(float x) { return x >= 0.f ? x : 0.2f * x; }
__device__ __forceinline__ float elu(float x)   { return x > 0.f ? x : expm1f(x); }
__device__ __forceinline__ void pdl_wait()    { asm volatile("griddepcontrol.wait;" ::: "memory"); }
__device__ __forceinline__ void pdl_trigger() { asm volatile("griddepcontrol.launch_dependents;" ::: "memory"); }

// ---------------- K1: proj (blocks 0..39) + scan w/ inline stats -------------
__global__ void k_main(const float* __restrict__ X, const float* __restrict__ E,
                       const float* __restrict__ H, const float* __restrict__ W,
                       const float* __restrict__ ax, const float* __restrict__ ae) {
    pdl_wait();   // previous replay's k_out restored zero-invariants
    if (blockIdx.x >= PROJ_BLOCKS) {
        // ---- scan: prefetch 8 H lines, wait for proj flag, then process ----
        int t = (blockIdx.x - PROJ_BLOCKS) * blockDim.x + threadIdx.x;
        const int stride = SCAN_BLOCKS * 256;
        const uint4* H4 = reinterpret_cast<const uint4*>(H);
        uint4 v[SCAN_ITERS];
#pragma unroll
        for (int it = 0; it < SCAN_ITERS; it++) v[it] = H4[t + it * stride];

        if (threadIdx.x == 0) {
            while (*(volatile int*)&g_proj_done < PROJ_BLOCKS) { }
        }
        __syncthreads();
        __threadfence();   // acquire proj writes

#pragma unroll
        for (int it = 0; it < SCAN_ITERS; it++) {
            uint4 h = v[it];
            if (h.x | h.y | h.z | h.w) {
                int base = (t + it * stride) * 4;
                unsigned c4[4] = {h.x, h.y, h.z, h.w};
#pragma unroll
                for (int c = 0; c < 4; c++) {
                    if (c4[c]) {
                        int lin = base + c;
                        int i = lin >> 11;        // / MM
                        int k = lin & (MM - 1);   // % MM
                        // inline softmax denominators (scatter)
                        float ex1 = __expf(leaky(g_sx[i] + g_se[k]));
                        atomicAdd(&g_npack[i * 16 + 1], ex1);
                        float ex2 = __expf(leaky(g_s1[k] + g_s2[i]));
                        atomicAdd(&g_colsum[k], ex2);
                        // adjacency lists
                        int p = atomicAdd(&g_row_cnt[i], 1);
                        if (p < ROW_CAP) g_row_edges[i * ROW_CAP + p] = k;
                        int q = atomicAdd(&g_col_cnt[k], 1);
                        if (q < COL_CAP) g_col_nodes[k * COL_CAP + q] = i;
                    }
                }
            }
        }
        pdl_trigger();
        return;
    }

    // ---- projection: rows 0..NN-1 -> X, NN..NN+MM-1 -> E ----
    __shared__ float sW[DD * DHH];
    __shared__ float sax[2 * DHH], sae[2 * DHH];
    for (int j = threadIdx.x; j < DD * DHH; j += blockDim.x) sW[j] = W[j];
    if (threadIdx.x < 2 * DHH) {
        sax[threadIdx.x] = ax[threadIdx.x];
        sae[threadIdx.x] = ae[threadIdx.x];
    }
    __syncthreads();

    int r = blockIdx.x * blockDim.x + threadIdx.x;   // 0..10239
    if (r < DHH) { g_empty_wx[r] = 0.f; g_empty_en[r] = 0.f; }

    const float* src = (r < NN) ? (X + (size_t)r * DD)
                                : (E + (size_t)(r - NN) * DD);
    float acc[DHH];
#pragma unroll
    for (int d = 0; d < DHH; d++) acc[d] = 0.f;

    const float4* Ar = reinterpret_cast<const float4*>(src);
#pragma unroll 4
    for (int j4 = 0; j4 < DD / 4; j4++) {
        float4 x = Ar[j4];
        int j = 4 * j4;
#pragma unroll
        for (int d = 0; d < DHH; d++) acc[d] += x.x * sW[(j + 0) * DHH + d];
#pragma unroll
        for (int d = 0; d < DHH; d++) acc[d] += x.y * sW[(j + 1) * DHH + d];
#pragma unroll
        for (int d = 0; d < DHH; d++) acc[d] += x.z * sW[(j + 2) * DHH + d];
#pragma unroll
        for (int d = 0; d < DHH; d++) acc[d] += x.w * sW[(j + 3) * DHH + d];
    }

    if (r < NN) {
        float d1 = 0.f, d2 = 0.f;
#pragma unroll
        for (int d = 0; d < DHH; d++) {
            d1 += acc[d] * sax[d];          // alpha_x[:dh]
            d2 += acc[d] * sae[DHH + d];    // alpha_e[dh:]
        }
        g_sx[r] = d1; g_s2[r] = d2;
        float4* np = reinterpret_cast<float4*>(&g_npack[r * 16]);
        np[0] = make_float4(d1, 0.f, d2, 0.f);   // [1] accumulates rowSum
        np[1] = make_float4(acc[0], acc[1], acc[2], acc[3]);
        np[2] = make_float4(acc[4], acc[5], acc[6], acc[7]);
    } else {
        int k = r - NN;
        float d1 = 0.f, d2 = 0.f;
#pragma unroll
        for (int d = 0; d < DHH; d++) {
            d1 += acc[d] * sax[DHH + d];    // alpha_x[dh:]
            d2 += acc[d] * sae[d];          // alpha_e[:dh]
        }
        g_se[k] = d1; g_s1[k] = d2;
    }

    // signal scan blocks
    __syncthreads();
    if (threadIdx.x == 0) {
        __threadfence();
        atomicAdd(&g_proj_done, 1);
    }
    pdl_trigger();
}

// ---------------- K2: empty-node detection -> empty_wx -----------------------
__global__ void k_prep() {
    pdl_wait();
    int i = blockIdx.x * blockDim.x + threadIdx.x;   // NN threads
    if (g_row_cnt[i] == 0) {
#pragma unroll
        for (int d = 0; d < DHH; d++)
            atomicAdd(&g_empty_wx[d], g_npack[i * 16 + 4 + d]);
    }
    pdl_trigger();
}

// ---------------- K3: E_new (warp/edge) + scatter into xacc ------------------
__global__ void k_enew() {
    pdl_wait();
    int gid = blockIdx.x * blockDim.x + threadIdx.x;
    int k = gid >> 5;                                 // exactly MM warps
    int lane = gid & 31;
    int cnt = min(g_col_cnt[k], COL_CAP);
    const float invM = 1.f / MM;

    if (cnt == 0) {
        if (lane < DHH)
            atomicAdd(&g_empty_en[lane], elu(invM * g_empty_wx[lane]));
        pdl_trigger();
        return;
    }

    float sek = g_se[k], s1k = g_s1[k];
    float invColS = 1.f / g_colsum[k];
    float acc[DHH];
#pragma unroll
    for (int d = 0; d < DHH; d++) acc[d] = 0.f;

    int   iv[COL_CAP / 32];
    float wsv[COL_CAP / 32];
    int nit = 0;
    for (int j = lane; j < cnt; j += 32) {
        int i = g_col_nodes[k * COL_CAP + j];
        const float4* np = reinterpret_cast<const float4*>(&g_npack[i * 16]);
        float4 p0 = np[0], p1 = np[1], p2 = np[2];
        float wt = __fdividef(__expf(leaky(p0.x + sek)), p0.y);  // node->edge att
        acc[0] += wt * p1.x; acc[1] += wt * p1.y; acc[2] += wt * p1.z; acc[3] += wt * p1.w;
        acc[4] += wt * p2.x; acc[5] += wt * p2.y; acc[6] += wt * p2.z; acc[7] += wt * p2.w;
        iv[nit] = i;
        wsv[nit] = __expf(leaky(s1k + p0.z)) * invColS;          // edge->node att
        nit++;
    }

    // xor-butterfly: ALL lanes end with the full sums
#pragma unroll
    for (int d = 0; d < DHH; d++)
#pragma unroll
        for (int off = 16; off > 0; off >>= 1)
            acc[d] += __shfl_xor_sync(0xffffffffu, acc[d], off);

    float4 ew0 = *reinterpret_cast<const float4*>(&g_empty_wx[0]);
    float4 ew1 = *reinterpret_cast<const float4*>(&g_empty_wx[4]);
    float en[DHH];
    en[0] = elu(acc[0] + invM * ew0.x); en[1] = elu(acc[1] + invM * ew0.y);
    en[2] = elu(acc[2] + invM * ew0.z); en[3] = elu(acc[3] + invM * ew0.w);
    en[4] = elu(acc[4] + invM * ew1.x); en[5] = elu(acc[5] + invM * ew1.y);
    en[6] = elu(acc[6] + invM * ew1.z); en[7] = elu(acc[7] + invM * ew1.w);

    // scatter: xacc[i][d] += w_edge(k,i) * Enew[k][d]
    for (int t = 0; t < nit; t++) {
        float* dst = &g_xacc[iv[t] * DHH];
        float w = wsv[t];
#pragma unroll
        for (int d = 0; d < DHH; d++) atomicAdd(dst + d, w * en[d]);
    }
    pdl_trigger();
}

// ---------------- K4: epilogue + full state cleanup --------------------------
__global__ void k_out(float* __restrict__ out) {
    pdl_wait();
    int gid = blockIdx.x * blockDim.x + threadIdx.x;   // NN*8 threads
    int u = gid & 7;
    const float invN = 1.f / NN;
    out[gid] = elu(g_xacc[gid] + invN * g_empty_en[u]);
    // ---- restore zero-invariants for next replay ----
    g_xacc[gid] = 0.f;
    if (gid < NN) g_row_cnt[gid] = 0;
    if (gid < MM) { g_col_cnt[gid] = 0; g_colsum[gid] = 0.f; }
    if (gid == 0) g_proj_done = 0;
    pdl_trigger();
}

// -----------------------------------------------------------------------------
extern "C" void kernel_launch(void* const* d_in, const int* in_sizes, int n_in,
                              void* d_out, int out_size) {
    const float* X  = (const float*)d_in[0];
    const float* E  = (const float*)d_in[1];
    const float* H  = (const float*)d_in[2];
    const float* W  = (const float*)d_in[3];
    const float* ax = (const float*)d_in[4];
    const float* ae = (const float*)d_in[5];
    float* out = (float*)d_out;

    cudaLaunchAttribute attr;
    attr.id = cudaLaunchAttributeProgrammaticStreamSerialization;
    attr.val.programmaticStreamSerializationAllowed = 1;

    cudaLaunchConfig_t cfg = {};
    cfg.blockDim = dim3(256);
    cfg.dynamicSmemBytes = 0;
    cfg.stream = 0;
    cfg.attrs = &attr;
    cfg.numAttrs = 1;

    cfg.gridDim = dim3(PROJ_BLOCKS + SCAN_BLOCKS);
    cudaLaunchKernelEx(&cfg, k_main, X, E, H, W, ax, ae);

    cfg.gridDim = dim3(NN / 256);
    cudaLaunchKernelEx(&cfg, k_prep);

    cfg.gridDim = dim3(MM * 32 / 256);
    cudaLaunchKernelEx(&cfg, k_enew);

    cfg.gridDim = dim3(NN * 8 / 256);
    cudaLaunchKernelEx(&cfg, k_out, out);
}

// round 8
// speedup vs baseline: 1.6320x; 1.6320x over previous
#include <cuda_runtime.h>

#define NN 8192
#define MM 2048
#define DD 256
#define DHH 8
#define ROW_CAP 64
#define COL_CAP 128
#define PROJ_BLOCKS 40          // (NN+MM)/256
#define SCAN_BLOCKS 2048
#define SCAN_ITERS 8            // NN*MM/4 / (SCAN_BLOCKS*256)

// ---------------- scratch (static device globals; zero-init at load) ---------
__device__ float g_sx[NN];
__device__ float g_s2[NN];
__device__ float g_se[MM];
__device__ float g_s1[MM];
__device__ int   g_row_cnt[NN];        // zero at entry; re-zeroed in k_out
__device__ int   g_col_cnt[MM];
__device__ __align__(16) int g_row_edges[NN * ROW_CAP];
__device__ int   g_col_nodes[MM * COL_CAP];
// packed per-node record: [sx, 1/rowSum, s2, 0, WX0..7, pad4] (stride 16 floats)
__device__ __align__(16) float g_npack[NN * 16];
// per-edge: [1]=1/colSum
__device__ __align__(16) float g_epack[MM * 16];
__device__ __align__(16) float g_empty_wx[DHH];     // zeroed by proj each replay
__device__ __align__(16) float g_empty_en[DHH];
__device__ __align__(16) float g_xacc[NN * DHH];    // zero at entry; re-zeroed in k_out

__device__ __forceinline__ float leaky(float x) { return x >= 0.f ? x : 0.2f * x; }
__device__ __forceinline__ float elu(float x)   { return x > 0.f ? x : expm1f(x); }
__device__ __forceinline__ void pdl_wait()    { asm volatile("griddepcontrol.wait;" ::: "memory"); }
__device__ __forceinline__ void pdl_trigger() { asm volatile("griddepcontrol.launch_dependents;" ::: "memory"); }

// ---------------- K1: fused projection + H scan (independent block groups) ---
__global__ void k_main(const float* __restrict__ X, const float* __restrict__ E,
                       const float* __restrict__ H, const float* __restrict__ W,
                       const float* __restrict__ ax, const float* __restrict__ ae) {
    pdl_wait();   // previous replay's k_out restored zero-invariants
    if (blockIdx.x >= PROJ_BLOCKS) {
        int t = (blockIdx.x - PROJ_BLOCKS) * blockDim.x + threadIdx.x;
        const int stride = SCAN_BLOCKS * 256;
        const uint4* H4 = reinterpret_cast<const uint4*>(H);
        uint4 v[SCAN_ITERS];
#pragma unroll
        for (int it = 0; it < SCAN_ITERS; it++) v[it] = H4[t + it * stride];
#pragma unroll
        for (int it = 0; it < SCAN_ITERS; it++) {
            uint4 h = v[it];
            if (h.x | h.y | h.z | h.w) {
                int base = (t + it * stride) * 4;
                unsigned c4[4] = {h.x, h.y, h.z, h.w};
#pragma unroll
                for (int c = 0; c < 4; c++) {
                    if (c4[c]) {
                        int lin = base + c;
                        int i = lin >> 11;        // / MM
                        int k = lin & (MM - 1);   // % MM
                        int p = atomicAdd(&g_row_cnt[i], 1);
                        if (p < ROW_CAP) g_row_edges[i * ROW_CAP + p] = k;
                        int q = atomicAdd(&g_col_cnt[k], 1);
                        if (q < COL_CAP) g_col_nodes[k * COL_CAP + q] = i;
                    }
                }
            }
        }
        pdl_trigger();
        return;
    }

    // ---- projection: rows 0..NN-1 -> X, NN..NN+MM-1 -> E ----
    __shared__ float sW[DD * DHH];
    __shared__ float sax[2 * DHH], sae[2 * DHH];
    for (int j = threadIdx.x; j < DD * DHH; j += blockDim.x) sW[j] = W[j];
    if (threadIdx.x < 2 * DHH) {
        sax[threadIdx.x] = ax[threadIdx.x];
        sae[threadIdx.x] = ae[threadIdx.x];
    }
    __syncthreads();

    int r = blockIdx.x * blockDim.x + threadIdx.x;   // 0..10239
    if (r < DHH) { g_empty_wx[r] = 0.f; g_empty_en[r] = 0.f; }

    const float* src = (r < NN) ? (X + (size_t)r * DD)
                                : (E + (size_t)(r - NN) * DD);
    float acc[DHH];
#pragma unroll
    for (int d = 0; d < DHH; d++) acc[d] = 0.f;

    const float4* Ar = reinterpret_cast<const float4*>(src);
#pragma unroll 4
    for (int j4 = 0; j4 < DD / 4; j4++) {
        float4 x = Ar[j4];
        int j = 4 * j4;
#pragma unroll
        for (int d = 0; d < DHH; d++) acc[d] += x.x * sW[(j + 0) * DHH + d];
#pragma unroll
        for (int d = 0; d < DHH; d++) acc[d] += x.y * sW[(j + 1) * DHH + d];
#pragma unroll
        for (int d = 0; d < DHH; d++) acc[d] += x.z * sW[(j + 2) * DHH + d];
#pragma unroll
        for (int d = 0; d < DHH; d++) acc[d] += x.w * sW[(j + 3) * DHH + d];
    }

    if (r < NN) {
        float d1 = 0.f, d2 = 0.f;
#pragma unroll
        for (int d = 0; d < DHH; d++) {
            d1 += acc[d] * sax[d];          // alpha_x[:dh]
            d2 += acc[d] * sae[DHH + d];    // alpha_e[dh:]
        }
        g_sx[r] = d1; g_s2[r] = d2;
        float4* np = reinterpret_cast<float4*>(&g_npack[r * 16]);
        np[0] = make_float4(d1, 0.f, d2, 0.f);
        np[1] = make_float4(acc[0], acc[1], acc[2], acc[3]);
        np[2] = make_float4(acc[4], acc[5], acc[6], acc[7]);
    } else {
        int k = r - NN;
        float d1 = 0.f, d2 = 0.f;
#pragma unroll
        for (int d = 0; d < DHH; d++) {
            d1 += acc[d] * sax[DHH + d];    // alpha_x[dh:]
            d2 += acc[d] * sae[d];          // alpha_e[:dh]
        }
        g_se[k] = d1; g_s1[k] = d2;
    }
    pdl_trigger();
}

// ---------------- K2: row exp-sums (8 lanes/node) + col exp-sums (8/edge) ----
__global__ void k_stats() {
    pdl_wait();
    int gid = blockIdx.x * blockDim.x + threadIdx.x;   // (NN+MM)*8 threads
    if (gid < NN * 8) {
        int i = gid >> 3, l8 = gid & 7;
        int cnt = min(g_row_cnt[i], ROW_CAP);
        if (cnt == 0) {
            atomicAdd(&g_empty_wx[l8], g_npack[i * 16 + 4 + l8]);
        } else {
            float sxi = g_sx[i];
            // batch: indices first (MLP=8), then se gathers (MLP=8), then exps
            int idx[8];
#pragma unroll
            for (int t = 0; t < 8; t++) {
                int j = l8 + 8 * t;
                idx[t] = (j < cnt) ? g_row_edges[i * ROW_CAP + j] : -1;
            }
            float sev[8];
#pragma unroll
            for (int t = 0; t < 8; t++)
                sev[t] = (idx[t] >= 0) ? g_se[idx[t]] : 0.f;
            float s = 0.f;
#pragma unroll
            for (int t = 0; t < 8; t++)
                if (idx[t] >= 0) s += __expf(leaky(sxi + sev[t]));
            s += __shfl_xor_sync(0xffffffffu, s, 4);
            s += __shfl_xor_sync(0xffffffffu, s, 2);
            s += __shfl_xor_sync(0xffffffffu, s, 1);
            if (l8 == 0) g_npack[i * 16 + 1] = 1.f / s;
        }
    } else {
        int g2 = gid - NN * 8;
        int k = g2 >> 3, l8 = g2 & 7;
        int cnt = min(g_col_cnt[k], COL_CAP);
        if (cnt > 0) {
            float s1k = g_s1[k];
            float s = 0.f;
            for (int base = 0; base < cnt; base += 32) {   // 4 per lane per chunk
                int idx[4];
#pragma unroll
                for (int t = 0; t < 4; t++) {
                    int j = base + l8 + 8 * t;
                    idx[t] = (j < cnt) ? g_col_nodes[k * COL_CAP + j] : -1;
                }
                float sv[4];
#pragma unroll
                for (int t = 0; t < 4; t++)
                    sv[t] = (idx[t] >= 0) ? g_s2[idx[t]] : 0.f;
#pragma unroll
                for (int t = 0; t < 4; t++)
                    if (idx[t] >= 0) s += __expf(leaky(s1k + sv[t]));
            }
            s += __shfl_xor_sync(0xffffffffu, s, 4);
            s += __shfl_xor_sync(0xffffffffu, s, 2);
            s += __shfl_xor_sync(0xffffffffu, s, 1);
            if (l8 == 0) g_epack[k * 16 + 1] = 1.f / s;
        }
    }
    pdl_trigger();
}

// ---------------- K3: E_new (warp/edge) + scatter into xacc ------------------
__global__ void k_enew() {
    pdl_wait();
    int gid = blockIdx.x * blockDim.x + threadIdx.x;
    int k = gid >> 5;                                 // exactly MM warps
    int lane = gid & 31;
    int cnt = min(g_col_cnt[k], COL_CAP);
    const float invM = 1.f / MM;

    if (cnt == 0) {
        if (lane < DHH)
            atomicAdd(&g_empty_en[lane], elu(invM * g_empty_wx[lane]));
        pdl_trigger();
        return;
    }

    float sek = g_se[k], s1k = g_s1[k];
    float invColS = g_epack[k * 16 + 1];
    float acc[DHH];
#pragma unroll
    for (int d = 0; d < DHH; d++) acc[d] = 0.f;

    int   iv[4];
    float wsv[4];
#pragma unroll
    for (int t = 0; t < 4; t++) {
        int j = lane + 32 * t;
        bool act = (j < cnt);
        int i = act ? g_col_nodes[k * COL_CAP + j] : 0;
        iv[t] = act ? i : -1;
        if (act) {
            const float4* np = reinterpret_cast<const float4*>(&g_npack[i * 16]);
            float4 p0 = np[0], p1 = np[1], p2 = np[2];
            float wt = __expf(leaky(p0.x + sek)) * p0.y;         // node->edge att
            acc[0] += wt * p1.x; acc[1] += wt * p1.y; acc[2] += wt * p1.z; acc[3] += wt * p1.w;
            acc[4] += wt * p2.x; acc[5] += wt * p2.y; acc[6] += wt * p2.z; acc[7] += wt * p2.w;
            wsv[t] = __expf(leaky(s1k + p0.z)) * invColS;        // edge->node att
        } else {
            wsv[t] = 0.f;
        }
    }

    // xor-butterfly: ALL lanes end with the full sums
#pragma unroll
    for (int d = 0; d < DHH; d++)
#pragma unroll
        for (int off = 16; off > 0; off >>= 1)
            acc[d] += __shfl_xor_sync(0xffffffffu, acc[d], off);

    float4 ew0 = *reinterpret_cast<const float4*>(&g_empty_wx[0]);
    float4 ew1 = *reinterpret_cast<const float4*>(&g_empty_wx[4]);
    float en[DHH];
    en[0] = elu(acc[0] + invM * ew0.x); en[1] = elu(acc[1] + invM * ew0.y);
    en[2] = elu(acc[2] + invM * ew0.z); en[3] = elu(acc[3] + invM * ew0.w);
    en[4] = elu(acc[4] + invM * ew1.x); en[5] = elu(acc[5] + invM * ew1.y);
    en[6] = elu(acc[6] + invM * ew1.z); en[7] = elu(acc[7] + invM * ew1.w);

    // scatter: xacc[i][d] += w_edge(k,i) * Enew[k][d]
#pragma unroll
    for (int t = 0; t < 4; t++) {
        if (iv[t] >= 0) {
            float* dst = &g_xacc[iv[t] * DHH];
            float w = wsv[t];
#pragma unroll
            for (int d = 0; d < DHH; d++) atomicAdd(dst + d, w * en[d]);
        }
    }
    pdl_trigger();
}

// ---------------- K4: epilogue (float4/thread) + vectorized cleanup ----------
__global__ void k_out(float* __restrict__ out) {
    pdl_wait();
    int gid = blockIdx.x * blockDim.x + threadIdx.x;   // NN*DHH/4 threads
    const float invN = 1.f / NN;
    int dbase = (gid * 4) & 7;                          // 0 or 4
    float4 en = *reinterpret_cast<const float4*>(&g_empty_en[dbase]);
    float4 xa = reinterpret_cast<const float4*>(g_xacc)[gid];
    float4 o;
    o.x = elu(xa.x + invN * en.x);
    o.y = elu(xa.y + invN * en.y);
    o.z = elu(xa.z + invN * en.z);
    o.w = elu(xa.w + invN * en.w);
    reinterpret_cast<float4*>(out)[gid] = o;
    // ---- restore zero-invariants for next replay (vectorized) ----
    reinterpret_cast<float4*>(g_xacc)[gid] = make_float4(0.f, 0.f, 0.f, 0.f);
    if (gid < NN / 4) reinterpret_cast<int4*>(g_row_cnt)[gid] = make_int4(0, 0, 0, 0);
    if (gid < MM / 4) reinterpret_cast<int4*>(g_col_cnt)[gid] = make_int4(0, 0, 0, 0);
    pdl_trigger();
}

// -----------------------------------------------------------------------------
extern "C" void kernel_launch(void* const* d_in, const int* in_sizes, int n_in,
                              void* d_out, int out_size) {
    const float* X  = (const float*)d_in[0];
    const float* E  = (const float*)d_in[1];
    const float* H  = (const float*)d_in[2];
    const float* W  = (const float*)d_in[3];
    const float* ax = (const float*)d_in[4];
    const float* ae = (const float*)d_in[5];
    float* out = (float*)d_out;

    cudaLaunchAttribute attr;
    attr.id = cudaLaunchAttributeProgrammaticStreamSerialization;
    attr.val.programmaticStreamSerializationAllowed = 1;

    cudaLaunchConfig_t cfg = {};
    cfg.blockDim = dim3(256);
    cfg.dynamicSmemBytes = 0;
    cfg.stream = 0;
    cfg.attrs = &attr;
    cfg.numAttrs = 1;

    cfg.gridDim = dim3(PROJ_BLOCKS + SCAN_BLOCKS);
    cudaLaunchKernelEx(&cfg, k_main, X, E, H, W, ax, ae);

    cfg.gridDim = dim3((NN + MM) * 8 / 256);
    cudaLaunchKernelEx(&cfg, k_stats);

    cfg.gridDim = dim3(MM * 32 / 256);
    cudaLaunchKernelEx(&cfg, k_enew);

    cfg.gridDim = dim3(NN * DHH / 4 / 256);
    cudaLaunchKernelEx(&cfg, k_out, out);
}

// round 9
// speedup vs baseline: 1.7184x; 1.0529x over previous
#include <cuda_runtime.h>

#define NN 8192
#define MM 2048
#define DD 256
#define DHH 8
#define ROW_CAP 64
#define COL_CAP 128
#define PROJ_BLOCKS 40          // (NN+MM)/256
#define SCAN_BLOCKS 2048
#define SCAN_ITERS 8            // NN*MM/4 / (SCAN_BLOCKS*256)

// ---------------- scratch (static device globals; zero-init at load) ---------
__device__ float g_sx[NN];
__device__ float g_s2[NN];
__device__ float g_se[MM];
__device__ float g_s1[MM];
__device__ int   g_row_cnt[NN];        // zero at entry; re-zeroed in k_out
__device__ int   g_col_cnt[MM];
__device__ __align__(16) int g_row_edges[NN * ROW_CAP];
__device__ int   g_col_nodes[MM * COL_CAP];
// packed per-node record: [sx, 1/rowSum, s2, 0, WX0..7, pad4] (stride 16 floats)
__device__ __align__(16) float g_npack[NN * 16];
// per-edge: [1]=1/colSum
__device__ __align__(16) float g_epack[MM * 16];
__device__ __align__(16) float g_empty_wx[DHH];     // zeroed by proj each replay
__device__ __align__(16) float g_empty_en[DHH];
__device__ __align__(16) float g_xacc[NN * DHH];    // zero at entry; re-zeroed in k_out

__device__ __forceinline__ float leaky(float x) { return x >= 0.f ? x : 0.2f * x; }
// fast ELU: expm1f is a slow software path; __expf(x)-1 has ~6e-8 abs error (fine)
__device__ __forceinline__ float elu(float x)   { return x > 0.f ? x : __expf(x) - 1.f; }
__device__ __forceinline__ void pdl_wait()    { asm volatile("griddepcontrol.wait;" ::: "memory"); }
__device__ __forceinline__ void pdl_trigger() { asm volatile("griddepcontrol.launch_dependents;" ::: "memory"); }

// ---------------- K1: fused projection + H scan (independent block groups) ---
__global__ void k_main(const float* __restrict__ X, const float* __restrict__ E,
                       const float* __restrict__ H, const float* __restrict__ W,
                       const float* __restrict__ ax, const float* __restrict__ ae) {
    pdl_wait();   // previous replay's k_out restored zero-invariants
    if (blockIdx.x >= PROJ_BLOCKS) {
        int t = (blockIdx.x - PROJ_BLOCKS) * blockDim.x + threadIdx.x;
        const int stride = SCAN_BLOCKS * 256;
        const uint4* H4 = reinterpret_cast<const uint4*>(H);
        uint4 v[SCAN_ITERS];
#pragma unroll
        for (int it = 0; it < SCAN_ITERS; it++) v[it] = H4[t + it * stride];
#pragma unroll
        for (int it = 0; it < SCAN_ITERS; it++) {
            uint4 h = v[it];
            if (h.x | h.y | h.z | h.w) {
                int base = (t + it * stride) * 4;
                unsigned c4[4] = {h.x, h.y, h.z, h.w};
#pragma unroll
                for (int c = 0; c < 4; c++) {
                    if (c4[c]) {
                        int lin = base + c;
                        int i = lin >> 11;        // / MM
                        int k = lin & (MM - 1);   // % MM
                        int p = atomicAdd(&g_row_cnt[i], 1);
                        if (p < ROW_CAP) g_row_edges[i * ROW_CAP + p] = k;
                        int q = atomicAdd(&g_col_cnt[k], 1);
                        if (q < COL_CAP) g_col_nodes[k * COL_CAP + q] = i;
                    }
                }
            }
        }
        pdl_trigger();
        return;
    }

    // ---- projection: rows 0..NN-1 -> X, NN..NN+MM-1 -> E ----
    __shared__ float sW[DD * DHH];
    __shared__ float sax[2 * DHH], sae[2 * DHH];
    for (int j = threadIdx.x; j < DD * DHH; j += blockDim.x) sW[j] = W[j];
    if (threadIdx.x < 2 * DHH) {
        sax[threadIdx.x] = ax[threadIdx.x];
        sae[threadIdx.x] = ae[threadIdx.x];
    }
    __syncthreads();

    int r = blockIdx.x * blockDim.x + threadIdx.x;   // 0..10239
    if (r < DHH) { g_empty_wx[r] = 0.f; g_empty_en[r] = 0.f; }

    const float* src = (r < NN) ? (X + (size_t)r * DD)
                                : (E + (size_t)(r - NN) * DD);
    float acc[DHH];
#pragma unroll
    for (int d = 0; d < DHH; d++) acc[d] = 0.f;

    const float4* Ar = reinterpret_cast<const float4*>(src);
#pragma unroll 4
    for (int j4 = 0; j4 < DD / 4; j4++) {
        float4 x = Ar[j4];
        int j = 4 * j4;
#pragma unroll
        for (int d = 0; d < DHH; d++) acc[d] += x.x * sW[(j + 0) * DHH + d];
#pragma unroll
        for (int d = 0; d < DHH; d++) acc[d] += x.y * sW[(j + 1) * DHH + d];
#pragma unroll
        for (int d = 0; d < DHH; d++) acc[d] += x.z * sW[(j + 2) * DHH + d];
#pragma unroll
        for (int d = 0; d < DHH; d++) acc[d] += x.w * sW[(j + 3) * DHH + d];
    }

    if (r < NN) {
        float d1 = 0.f, d2 = 0.f;
#pragma unroll
        for (int d = 0; d < DHH; d++) {
            d1 += acc[d] * sax[d];          // alpha_x[:dh]
            d2 += acc[d] * sae[DHH + d];    // alpha_e[dh:]
        }
        g_sx[r] = d1; g_s2[r] = d2;
        float4* np = reinterpret_cast<float4*>(&g_npack[r * 16]);
        np[0] = make_float4(d1, 0.f, d2, 0.f);
        np[1] = make_float4(acc[0], acc[1], acc[2], acc[3]);
        np[2] = make_float4(acc[4], acc[5], acc[6], acc[7]);
    } else {
        int k = r - NN;
        float d1 = 0.f, d2 = 0.f;
#pragma unroll
        for (int d = 0; d < DHH; d++) {
            d1 += acc[d] * sax[DHH + d];    // alpha_x[dh:]
            d2 += acc[d] * sae[d];          // alpha_e[:dh]
        }
        g_se[k] = d1; g_s1[k] = d2;
    }
    pdl_trigger();
}

// ---------------- K2: row exp-sums (8 lanes/node) + col exp-sums (8/edge) ----
__global__ void k_stats() {
    pdl_wait();
    int gid = blockIdx.x * blockDim.x + threadIdx.x;   // (NN+MM)*8 threads
    if (gid < NN * 8) {
        int i = gid >> 3, l8 = gid & 7;
        int cnt = min(g_row_cnt[i], ROW_CAP);
        if (cnt == 0) {
            atomicAdd(&g_empty_wx[l8], g_npack[i * 16 + 4 + l8]);
        } else {
            float sxi = g_sx[i];
            float s = 0.f;
            for (int j = l8; j < cnt; j += 8)
                s += __expf(leaky(sxi + g_se[g_row_edges[i * ROW_CAP + j]]));
            s += __shfl_xor_sync(0xffffffffu, s, 4);
            s += __shfl_xor_sync(0xffffffffu, s, 2);
            s += __shfl_xor_sync(0xffffffffu, s, 1);
            if (l8 == 0) g_npack[i * 16 + 1] = 1.f / s;
        }
    } else {
        int g2 = gid - NN * 8;
        int k = g2 >> 3, l8 = g2 & 7;
        int cnt = min(g_col_cnt[k], COL_CAP);
        if (cnt > 0) {
            float s1k = g_s1[k];
            float s = 0.f;
            for (int j = l8; j < cnt; j += 8)
                s += __expf(leaky(s1k + g_s2[g_col_nodes[k * COL_CAP + j]]));
            s += __shfl_xor_sync(0xffffffffu, s, 4);
            s += __shfl_xor_sync(0xffffffffu, s, 2);
            s += __shfl_xor_sync(0xffffffffu, s, 1);
            if (l8 == 0) g_epack[k * 16 + 1] = 1.f / s;
        }
    }
    pdl_trigger();
}

// ---------------- K3: E_new (warp/edge) + scatter into xacc ------------------
__global__ void k_enew() {
    pdl_wait();
    int gid = blockIdx.x * blockDim.x + threadIdx.x;
    int k = gid >> 5;                                 // exactly MM warps
    int lane = gid & 31;
    int cnt = min(g_col_cnt[k], COL_CAP);
    const float invM = 1.f / MM;

    if (cnt == 0) {
        if (lane < DHH)
            atomicAdd(&g_empty_en[lane], elu(invM * g_empty_wx[lane]));
        pdl_trigger();
        return;
    }

    float sek = g_se[k], s1k = g_s1[k];
    float invColS = g_epack[k * 16 + 1];
    float acc[DHH];
#pragma unroll
    for (int d = 0; d < DHH; d++) acc[d] = 0.f;

    int   iv[COL_CAP / 32];
    float wsv[COL_CAP / 32];
    int nit = 0;
    for (int j = lane; j < cnt; j += 32) {
        int i = g_col_nodes[k * COL_CAP + j];
        const float4* np = reinterpret_cast<const float4*>(&g_npack[i * 16]);
        float4 p0 = np[0], p1 = np[1], p2 = np[2];
        float wt = __expf(leaky(p0.x + sek)) * p0.y;         // node->edge att
        acc[0] += wt * p1.x; acc[1] += wt * p1.y; acc[2] += wt * p1.z; acc[3] += wt * p1.w;
        acc[4] += wt * p2.x; acc[5] += wt * p2.y; acc[6] += wt * p2.z; acc[7] += wt * p2.w;
        iv[nit] = i;
        wsv[nit] = __expf(leaky(s1k + p0.z)) * invColS;      // edge->node att
        nit++;
    }

    // xor-butterfly: ALL lanes end with the full sums
#pragma unroll
    for (int d = 0; d < DHH; d++)
#pragma unroll
        for (int off = 16; off > 0; off >>= 1)
            acc[d] += __shfl_xor_sync(0xffffffffu, acc[d], off);

    float4 ew0 = *reinterpret_cast<const float4*>(&g_empty_wx[0]);
    float4 ew1 = *reinterpret_cast<const float4*>(&g_empty_wx[4]);
    float en[DHH];
    en[0] = elu(acc[0] + invM * ew0.x); en[1] = elu(acc[1] + invM * ew0.y);
    en[2] = elu(acc[2] + invM * ew0.z); en[3] = elu(acc[3] + invM * ew0.w);
    en[4] = elu(acc[4] + invM * ew1.x); en[5] = elu(acc[5] + invM * ew1.y);
    en[6] = elu(acc[6] + invM * ew1.z); en[7] = elu(acc[7] + invM * ew1.w);

    // scatter: xacc[i][d] += w_edge(k,i) * Enew[k][d]
    for (int t = 0; t < nit; t++) {
        float* dst = &g_xacc[iv[t] * DHH];
        float w = wsv[t];
#pragma unroll
        for (int d = 0; d < DHH; d++) atomicAdd(dst + d, w * en[d]);
    }
    pdl_trigger();
}

// ---------------- K4: epilogue + state cleanup -------------------------------
__global__ void k_out(float* __restrict__ out) {
    pdl_wait();
    int gid = blockIdx.x * blockDim.x + threadIdx.x;   // NN*8 threads
    int u = gid & 7;
    const float invN = 1.f / NN;
    out[gid] = elu(g_xacc[gid] + invN * g_empty_en[u]);
    // ---- restore zero-invariants for next replay ----
    g_xacc[gid] = 0.f;
    if (gid < NN) g_row_cnt[gid] = 0;
    if (gid < MM) g_col_cnt[gid] = 0;
    pdl_trigger();
}

// -----------------------------------------------------------------------------
extern "C" void kernel_launch(void* const* d_in, const int* in_sizes, int n_in,
                              void* d_out, int out_size) {
    const float* X  = (const float*)d_in[0];
    const float* E  = (const float*)d_in[1];
    const float* H  = (const float*)d_in[2];
    const float* W  = (const float*)d_in[3];
    const float* ax = (const float*)d_in[4];
    const float* ae = (const float*)d_in[5];
    float* out = (float*)d_out;

    cudaLaunchAttribute attr;
    attr.id = cudaLaunchAttributeProgrammaticStreamSerialization;
    attr.val.programmaticStreamSerializationAllowed = 1;

    cudaLaunchConfig_t cfg = {};
    cfg.blockDim = dim3(256);
    cfg.dynamicSmemBytes = 0;
    cfg.stream = 0;
    cfg.attrs = &attr;
    cfg.numAttrs = 1;

    cfg.gridDim = dim3(PROJ_BLOCKS + SCAN_BLOCKS);
    cudaLaunchKernelEx(&cfg, k_main, X, E, H, W, ax, ae);

    cfg.gridDim = dim3((NN + MM) * 8 / 256);
    cudaLaunchKernelEx(&cfg, k_stats);

    cfg.gridDim = dim3(MM * 32 / 256);
    cudaLaunchKernelEx(&cfg, k_enew);

    cfg.gridDim = dim3(NN * 8 / 256);
    cudaLaunchKernelEx(&cfg, k_out, out);
}

// round 10
// speedup vs baseline: 1.7246x; 1.0036x over previous
#include <cuda_runtime.h>

#define NN 8192
#define MM 2048
#define DD 256
#define DHH 8
#define ROW_CAP 64
#define COL_CAP 128
#define PROJ_BLOCKS 40          // (NN+MM)/256
#define SCAN_BLOCKS 2048
#define SCAN_ITERS 8            // NN*MM/4 / (SCAN_BLOCKS*256)

// ---------------- scratch (static device globals; zero-init at load) ---------
__device__ float g_sx[NN];
__device__ float g_s2[NN];
__device__ float g_se[MM];
__device__ float g_s1[MM];
__device__ int   g_row_cnt[NN];        // zero at entry; re-zeroed in k_out
__device__ int   g_col_cnt[MM];
__device__ __align__(16) int g_row_edges[NN * ROW_CAP];
__device__ int   g_col_nodes[MM * COL_CAP];
// packed per-node record: [sx, 1/rowSum, s2, 0, WX0..7, pad4] (stride 16 floats)
__device__ __align__(16) float g_npack[NN * 16];
__device__ __align__(16) float g_empty_wx[DHH];     // zeroed by proj each replay
__device__ __align__(16) float g_empty_en[DHH];
__device__ __align__(16) float g_xacc[NN * DHH];    // zero at entry; re-zeroed in k_out

__device__ __forceinline__ float leaky(float x) { return x >= 0.f ? x : 0.2f * x; }
// fast ELU: __expf(x)-1 (~6e-8 abs err vs expm1f; global tol is 1e-3)
__device__ __forceinline__ float elu(float x)   { return x > 0.f ? x : __expf(x) - 1.f; }
__device__ __forceinline__ void pdl_wait()    { asm volatile("griddepcontrol.wait;" ::: "memory"); }
__device__ __forceinline__ void pdl_trigger() { asm volatile("griddepcontrol.launch_dependents;" ::: "memory"); }

// ---------------- K1: fused projection + H scan (independent block groups) ---
__global__ void k_main(const float* __restrict__ X, const float* __restrict__ E,
                       const float* __restrict__ H, const float* __restrict__ W,
                       const float* __restrict__ ax, const float* __restrict__ ae) {
    pdl_wait();   // previous replay's k_out restored zero-invariants
    if (blockIdx.x >= PROJ_BLOCKS) {
        int t = (blockIdx.x - PROJ_BLOCKS) * blockDim.x + threadIdx.x;
        const int stride = SCAN_BLOCKS * 256;
        const uint4* H4 = reinterpret_cast<const uint4*>(H);
        uint4 v[SCAN_ITERS];
#pragma unroll
        for (int it = 0; it < SCAN_ITERS; it++) v[it] = H4[t + it * stride];
#pragma unroll
        for (int it = 0; it < SCAN_ITERS; it++) {
            uint4 h = v[it];
            if (h.x | h.y | h.z | h.w) {
                int base = (t + it * stride) * 4;
                unsigned c4[4] = {h.x, h.y, h.z, h.w};
#pragma unroll
                for (int c = 0; c < 4; c++) {
                    if (c4[c]) {
                        int lin = base + c;
                        int i = lin >> 11;        // / MM
                        int k = lin & (MM - 1);   // % MM
                        int p = atomicAdd(&g_row_cnt[i], 1);
                        if (p < ROW_CAP) g_row_edges[i * ROW_CAP + p] = k;
                        int q = atomicAdd(&g_col_cnt[k], 1);
                        if (q < COL_CAP) g_col_nodes[k * COL_CAP + q] = i;
                    }
                }
            }
        }
        pdl_trigger();
        return;
    }

    // ---- projection: rows 0..NN-1 -> X, NN..NN+MM-1 -> E ----
    __shared__ float sW[DD * DHH];
    __shared__ float sax[2 * DHH], sae[2 * DHH];
    for (int j = threadIdx.x; j < DD * DHH; j += blockDim.x) sW[j] = W[j];
    if (threadIdx.x < 2 * DHH) {
        sax[threadIdx.x] = ax[threadIdx.x];
        sae[threadIdx.x] = ae[threadIdx.x];
    }
    __syncthreads();

    int r = blockIdx.x * blockDim.x + threadIdx.x;   // 0..10239
    if (r < DHH) { g_empty_wx[r] = 0.f; g_empty_en[r] = 0.f; }

    const float* src = (r < NN) ? (X + (size_t)r * DD)
                                : (E + (size_t)(r - NN) * DD);
    float acc[DHH];
#pragma unroll
    for (int d = 0; d < DHH; d++) acc[d] = 0.f;

    const float4* Ar = reinterpret_cast<const float4*>(src);
#pragma unroll 4
    for (int j4 = 0; j4 < DD / 4; j4++) {
        float4 x = Ar[j4];
        int j = 4 * j4;
#pragma unroll
        for (int d = 0; d < DHH; d++) acc[d] += x.x * sW[(j + 0) * DHH + d];
#pragma unroll
        for (int d = 0; d < DHH; d++) acc[d] += x.y * sW[(j + 1) * DHH + d];
#pragma unroll
        for (int d = 0; d < DHH; d++) acc[d] += x.z * sW[(j + 2) * DHH + d];
#pragma unroll
        for (int d = 0; d < DHH; d++) acc[d] += x.w * sW[(j + 3) * DHH + d];
    }

    if (r < NN) {
        float d1 = 0.f, d2 = 0.f;
#pragma unroll
        for (int d = 0; d < DHH; d++) {
            d1 += acc[d] * sax[d];          // alpha_x[:dh]
            d2 += acc[d] * sae[DHH + d];    // alpha_e[dh:]
        }
        g_sx[r] = d1; g_s2[r] = d2;
        float4* np = reinterpret_cast<float4*>(&g_npack[r * 16]);
        np[0] = make_float4(d1, 0.f, d2, 0.f);
        np[1] = make_float4(acc[0], acc[1], acc[2], acc[3]);
        np[2] = make_float4(acc[4], acc[5], acc[6], acc[7]);
    } else {
        int k = r - NN;
        float d1 = 0.f, d2 = 0.f;
#pragma unroll
        for (int d = 0; d < DHH; d++) {
            d1 += acc[d] * sax[DHH + d];    // alpha_x[dh:]
            d2 += acc[d] * sae[d];          // alpha_e[:dh]
        }
        g_se[k] = d1; g_s1[k] = d2;
    }
    pdl_trigger();
}

// ---------------- K2: row exp-sums (8 lanes/node) + empty detection ----------
__global__ void k_stats() {
    pdl_wait();
    int gid = blockIdx.x * blockDim.x + threadIdx.x;   // NN*8 threads
    int i = gid >> 3, l8 = gid & 7;
    int cnt = min(g_row_cnt[i], ROW_CAP);
    if (cnt == 0) {
        atomicAdd(&g_empty_wx[l8], g_npack[i * 16 + 4 + l8]);
    } else {
        float sxi = g_sx[i];
        float s = 0.f;
        for (int j = l8; j < cnt; j += 8)
            s += __expf(leaky(sxi + g_se[g_row_edges[i * ROW_CAP + j]]));
        s += __shfl_xor_sync(0xffffffffu, s, 4);
        s += __shfl_xor_sync(0xffffffffu, s, 2);
        s += __shfl_xor_sync(0xffffffffu, s, 1);
        if (l8 == 0) g_npack[i * 16 + 1] = 1.f / s;
    }
    pdl_trigger();
}

// ---------------- K3: E_new + col softmax (warp-local) + scatter -------------
__global__ void k_enew() {
    pdl_wait();
    int gid = blockIdx.x * blockDim.x + threadIdx.x;
    int k = gid >> 5;                                 // exactly MM warps
    int lane = gid & 31;
    int cnt = min(g_col_cnt[k], COL_CAP);
    const float invM = 1.f / MM;

    if (cnt == 0) {
        if (lane < DHH)
            atomicAdd(&g_empty_en[lane], elu(invM * g_empty_wx[lane]));
        pdl_trigger();
        return;
    }

    float sek = g_se[k], s1k = g_s1[k];
    float acc[DHH];
#pragma unroll
    for (int d = 0; d < DHH; d++) acc[d] = 0.f;

    int   iv[COL_CAP / 32];
    float wsv[COL_CAP / 32];   // un-normalized edge-side exps
    float colS = 0.f;
    int nit = 0;
    for (int j = lane; j < cnt; j += 32) {
        int i = g_col_nodes[k * COL_CAP + j];
        const float4* np = reinterpret_cast<const float4*>(&g_npack[i * 16]);
        float4 p0 = np[0], p1 = np[1], p2 = np[2];
        float wt = __expf(leaky(p0.x + sek)) * p0.y;         // node->edge att
        acc[0] += wt * p1.x; acc[1] += wt * p1.y; acc[2] += wt * p1.z; acc[3] += wt * p1.w;
        acc[4] += wt * p2.x; acc[5] += wt * p2.y; acc[6] += wt * p2.z; acc[7] += wt * p2.w;
        float e2 = __expf(leaky(s1k + p0.z));                // edge->node exp
        iv[nit] = i;
        wsv[nit] = e2;
        colS += e2;
        nit++;
    }

    // xor-butterfly: ALL lanes end with the full sums
    {
        float c = colS;
#pragma unroll
        for (int off = 16; off > 0; off >>= 1)
            c += __shfl_xor_sync(0xffffffffu, c, off);
        colS = c;
    }
#pragma unroll
    for (int d = 0; d < DHH; d++)
#pragma unroll
        for (int off = 16; off > 0; off >>= 1)
            acc[d] += __shfl_xor_sync(0xffffffffu, acc[d], off);

    float invColS = __fdividef(1.f, colS);
    float4 ew0 = *reinterpret_cast<const float4*>(&g_empty_wx[0]);
    float4 ew1 = *reinterpret_cast<const float4*>(&g_empty_wx[4]);
    float en[DHH];
    en[0] = elu(acc[0] + invM * ew0.x); en[1] = elu(acc[1] + invM * ew0.y);
    en[2] = elu(acc[2] + invM * ew0.z); en[3] = elu(acc[3] + invM * ew0.w);
    en[4] = elu(acc[4] + invM * ew1.x); en[5] = elu(acc[5] + invM * ew1.y);
    en[6] = elu(acc[6] + invM * ew1.z); en[7] = elu(acc[7] + invM * ew1.w);

    // scatter: xacc[i][d] += w_edge(k,i) * Enew[k][d]
    for (int t = 0; t < nit; t++) {
        float* dst = &g_xacc[iv[t] * DHH];
        float w = wsv[t] * invColS;
#pragma unroll
        for (int d = 0; d < DHH; d++) atomicAdd(dst + d, w * en[d]);
    }
    pdl_trigger();
}

// ---------------- K4: epilogue (2 elems/thread, MLP=2) + cleanup -------------
__global__ void k_out(float* __restrict__ out) {
    pdl_wait();
    const int HALF = NN * DHH / 2;                     // 32768
    int gid = blockIdx.x * blockDim.x + threadIdx.x;   // HALF threads
    int g2 = gid + HALF;
    const float invN = 1.f / NN;
    // two independent loads in flight
    float xa0 = g_xacc[gid];
    float xa1 = g_xacc[g2];
    float en0 = g_empty_en[gid & 7];
    float en1 = g_empty_en[g2 & 7];
    out[gid] = elu(xa0 + invN * en0);
    out[g2]  = elu(xa1 + invN * en1);
    // ---- restore zero-invariants for next replay ----
    g_xacc[gid] = 0.f;
    g_xacc[g2]  = 0.f;
    if (gid < NN) g_row_cnt[gid] = 0;
    if (gid < MM) g_col_cnt[gid] = 0;
    pdl_trigger();
}

// -----------------------------------------------------------------------------
extern "C" void kernel_launch(void* const* d_in, const int* in_sizes, int n_in,
                              void* d_out, int out_size) {
    const float* X  = (const float*)d_in[0];
    const float* E  = (const float*)d_in[1];
    const float* H  = (const float*)d_in[2];
    const float* W  = (const float*)d_in[3];
    const float* ax = (const float*)d_in[4];
    const float* ae = (const float*)d_in[5];
    float* out = (float*)d_out;

    cudaLaunchAttribute attr;
    attr.id = cudaLaunchAttributeProgrammaticStreamSerialization;
    attr.val.programmaticStreamSerializationAllowed = 1;

    cudaLaunchConfig_t cfg = {};
    cfg.blockDim = dim3(256);
    cfg.dynamicSmemBytes = 0;
    cfg.stream = 0;
    cfg.attrs = &attr;
    cfg.numAttrs = 1;

    cfg.gridDim = dim3(PROJ_BLOCKS + SCAN_BLOCKS);
    cudaLaunchKernelEx(&cfg, k_main, X, E, H, W, ax, ae);

    cfg.gridDim = dim3(NN * 8 / 256);
    cudaLaunchKernelEx(&cfg, k_stats);

    cfg.gridDim = dim3(MM * 32 / 256);
    cudaLaunchKernelEx(&cfg, k_enew);

    cfg.gridDim = dim3(NN * DHH / 2 / 256);
    cudaLaunchKernelEx(&cfg, k_out, out);
}

// round 11
// speedup vs baseline: 1.7371x; 1.0073x over previous
#include <cuda_runtime.h>

#define NN 8192
#define MM 2048
#define DD 256
#define DHH 8
#define ROW_CAP 64
#define COL_CAP 128
#define PROJ_BLOCKS 40          // (NN+MM)/256
#define SCAN_BLOCKS 2048
#define SCAN_ITERS 8            // NN*MM/4 / (SCAN_BLOCKS*256)

// ---------------- scratch (static device globals; zero-init at load) ---------
__device__ float g_sx[NN];
__device__ float g_s2[NN];
__device__ float g_se[MM];
__device__ float g_s1[MM];
__device__ int   g_row_cnt[NN];        // zero at entry; re-zeroed in k_out
__device__ int   g_col_cnt[MM];
__device__ __align__(16) int g_row_edges[NN * ROW_CAP];
__device__ int   g_col_nodes[MM * COL_CAP];
// packed per-node record: [sx, 1/rowSum, s2, 0, WX0..7, pad4] (stride 16 floats)
__device__ __align__(16) float g_npack[NN * 16];
__device__ __align__(16) float g_empty_wx[DHH];     // zeroed by proj each replay
__device__ __align__(16) float g_empty_en[DHH];
__device__ __align__(16) float g_xacc[NN * DHH];    // zero at entry; re-zeroed in k_out

__device__ __forceinline__ float leaky(float x) { return x >= 0.f ? x : 0.2f * x; }
// fast ELU: __expf(x)-1 (~6e-8 abs err vs expm1f; global tol is 1e-3)
__device__ __forceinline__ float elu(float x)   { return x > 0.f ? x : __expf(x) - 1.f; }
__device__ __forceinline__ void pdl_wait()    { asm volatile("griddepcontrol.wait;" ::: "memory"); }
__device__ __forceinline__ void pdl_trigger() { asm volatile("griddepcontrol.launch_dependents;" ::: "memory"); }

// ---------------- K1: fused projection + H scan (independent block groups) ---
// Pre-wait: all input-only reads/compute (overlaps prior replay's k_out).
// Post-wait: writes to persistent state.
__global__ void k_main(const float* __restrict__ X, const float* __restrict__ E,
                       const float* __restrict__ H, const float* __restrict__ W,
                       const float* __restrict__ ax, const float* __restrict__ ae) {
    if (blockIdx.x >= PROJ_BLOCKS) {
        // ---- scan: H loads PRE-wait (input-only), atomics POST-wait ----
        int t = (blockIdx.x - PROJ_BLOCKS) * blockDim.x + threadIdx.x;
        const int stride = SCAN_BLOCKS * 256;
        const uint4* H4 = reinterpret_cast<const uint4*>(H);
        uint4 v[SCAN_ITERS];
#pragma unroll
        for (int it = 0; it < SCAN_ITERS; it++) v[it] = H4[t + it * stride];

        pdl_wait();        // prior replay's k_out re-zeroed counters
        pdl_trigger();     // let k_stats launch early

#pragma unroll
        for (int it = 0; it < SCAN_ITERS; it++) {
            uint4 h = v[it];
            if (h.x | h.y | h.z | h.w) {
                int base = (t + it * stride) * 4;
                unsigned c4[4] = {h.x, h.y, h.z, h.w};
#pragma unroll
                for (int c = 0; c < 4; c++) {
                    if (c4[c]) {
                        int lin = base + c;
                        int i = lin >> 11;        // / MM
                        int k = lin & (MM - 1);   // % MM
                        int p = atomicAdd(&g_row_cnt[i], 1);
                        if (p < ROW_CAP) g_row_edges[i * ROW_CAP + p] = k;
                        int q = atomicAdd(&g_col_cnt[k], 1);
                        if (q < COL_CAP) g_col_nodes[k * COL_CAP + q] = i;
                    }
                }
            }
        }
        return;
    }

    // ---- projection: full compute PRE-wait (inputs only) ----
    __shared__ float sW[DD * DHH];
    __shared__ float sax[2 * DHH], sae[2 * DHH];
    for (int j = threadIdx.x; j < DD * DHH; j += blockDim.x) sW[j] = W[j];
    if (threadIdx.x < 2 * DHH) {
        sax[threadIdx.x] = ax[threadIdx.x];
        sae[threadIdx.x] = ae[threadIdx.x];
    }
    __syncthreads();

    int r = blockIdx.x * blockDim.x + threadIdx.x;   // 0..10239
    const float* src = (r < NN) ? (X + (size_t)r * DD)
                                : (E + (size_t)(r - NN) * DD);
    float acc[DHH];
#pragma unroll
    for (int d = 0; d < DHH; d++) acc[d] = 0.f;

    const float4* Ar = reinterpret_cast<const float4*>(src);
#pragma unroll 4
    for (int j4 = 0; j4 < DD / 4; j4++) {
        float4 x = Ar[j4];
        int j = 4 * j4;
#pragma unroll
        for (int d = 0; d < DHH; d++) acc[d] += x.x * sW[(j + 0) * DHH + d];
#pragma unroll
        for (int d = 0; d < DHH; d++) acc[d] += x.y * sW[(j + 1) * DHH + d];
#pragma unroll
        for (int d = 0; d < DHH; d++) acc[d] += x.z * sW[(j + 2) * DHH + d];
#pragma unroll
        for (int d = 0; d < DHH; d++) acc[d] += x.w * sW[(j + 3) * DHH + d];
    }
    float d1 = 0.f, d2 = 0.f;
    if (r < NN) {
#pragma unroll
        for (int d = 0; d < DHH; d++) {
            d1 += acc[d] * sax[d];          // alpha_x[:dh]
            d2 += acc[d] * sae[DHH + d];    // alpha_e[dh:]
        }
    } else {
#pragma unroll
        for (int d = 0; d < DHH; d++) {
            d1 += acc[d] * sax[DHH + d];    // alpha_x[dh:]
            d2 += acc[d] * sae[d];          // alpha_e[:dh]
        }
    }

    pdl_wait();        // prior replay fully done -> safe to overwrite state
    pdl_trigger();

    if (r < DHH) { g_empty_wx[r] = 0.f; g_empty_en[r] = 0.f; }
    if (r < NN) {
        g_sx[r] = d1; g_s2[r] = d2;
        float4* np = reinterpret_cast<float4*>(&g_npack[r * 16]);
        np[0] = make_float4(d1, 0.f, d2, 0.f);
        np[1] = make_float4(acc[0], acc[1], acc[2], acc[3]);
        np[2] = make_float4(acc[4], acc[5], acc[6], acc[7]);
    } else {
        int k = r - NN;
        g_se[k] = d1; g_s1[k] = d2;
    }
}

// ---------------- K2: row exp-sums (8 lanes/node) + empty detection ----------
__global__ void k_stats() {
    pdl_wait();
    pdl_trigger();
    int gid = blockIdx.x * blockDim.x + threadIdx.x;   // NN*8 threads
    int i = gid >> 3, l8 = gid & 7;
    int cnt = min(g_row_cnt[i], ROW_CAP);
    if (cnt == 0) {
        atomicAdd(&g_empty_wx[l8], g_npack[i * 16 + 4 + l8]);
    } else {
        float sxi = g_sx[i];
        float s = 0.f;
        for (int j = l8; j < cnt; j += 8)
            s += __expf(leaky(sxi + g_se[g_row_edges[i * ROW_CAP + j]]));
        s += __shfl_xor_sync(0xffffffffu, s, 4);
        s += __shfl_xor_sync(0xffffffffu, s, 2);
        s += __shfl_xor_sync(0xffffffffu, s, 1);
        if (l8 == 0) g_npack[i * 16 + 1] = 1.f / s;
    }
}

// ---------------- K3: E_new + col softmax + scatter --------------------------
// Pre-wait: all k_main-sourced gathers + exps + colS (overlaps k_stats body).
// Post-wait: 1/rowSum + empty_wx reads, reductions, scatter.
__global__ void __launch_bounds__(256) k_enew() {
    int gid = blockIdx.x * blockDim.x + threadIdx.x;
    int k = gid >> 5;                                 // exactly MM warps
    int lane = gid & 31;
    // ---- pre-wait (depends only on k_main, complete by stream order) ----
    int cnt = min(g_col_cnt[k], COL_CAP);
    float sek = g_se[k], s1k = g_s1[k];

    int   iv[4];
    float e1v[4], e2v[4];
    float wx[4][DHH];
    float colS = 0.f;
#pragma unroll
    for (int t = 0; t < 4; t++) {
        int j = lane + 32 * t;
        bool act = (j < cnt);
        int i = act ? g_col_nodes[k * COL_CAP + j] : 0;
        iv[t] = act ? i : -1;
        const float4* np = reinterpret_cast<const float4*>(&g_npack[i * 16]);
        float4 p0 = np[0];                 // x=sx, z=s2 valid; y stale (ignored)
        float4 p1 = np[1], p2 = np[2];
        float e1 = act ? __expf(leaky(p0.x + sek)) : 0.f;
        float e2 = act ? __expf(leaky(s1k + p0.z)) : 0.f;
        e1v[t] = e1; e2v[t] = e2; colS += e2;
        wx[t][0] = p1.x; wx[t][1] = p1.y; wx[t][2] = p1.z; wx[t][3] = p1.w;
        wx[t][4] = p2.x; wx[t][5] = p2.y; wx[t][6] = p2.z; wx[t][7] = p2.w;
    }
#pragma unroll
    for (int off = 16; off > 0; off >>= 1)
        colS += __shfl_xor_sync(0xffffffffu, colS, off);

    pdl_wait();        // k_stats done: 1/rowSum + empty_wx final
    pdl_trigger();

    const float invM = 1.f / MM;
    if (cnt == 0) {
        if (lane < DHH)
            atomicAdd(&g_empty_en[lane], elu(invM * g_empty_wx[lane]));
        return;
    }

    // fetch fresh 1/rowSum scalars (MLP=4)
    float inv[4];
#pragma unroll
    for (int t = 0; t < 4; t++)
        inv[t] = (iv[t] >= 0) ? g_npack[iv[t] * 16 + 1] : 0.f;

    float acc[DHH];
#pragma unroll
    for (int d = 0; d < DHH; d++) acc[d] = 0.f;
#pragma unroll
    for (int t = 0; t < 4; t++) {
        float wt = e1v[t] * inv[t];
#pragma unroll
        for (int d = 0; d < DHH; d++) acc[d] += wt * wx[t][d];
    }
#pragma unroll
    for (int d = 0; d < DHH; d++)
#pragma unroll
        for (int off = 16; off > 0; off >>= 1)
            acc[d] += __shfl_xor_sync(0xffffffffu, acc[d], off);

    float invColS = __fdividef(1.f, colS);
    float4 ew0 = *reinterpret_cast<const float4*>(&g_empty_wx[0]);
    float4 ew1 = *reinterpret_cast<const float4*>(&g_empty_wx[4]);
    float en[DHH];
    en[0] = elu(acc[0] + invM * ew0.x); en[1] = elu(acc[1] + invM * ew0.y);
    en[2] = elu(acc[2] + invM * ew0.z); en[3] = elu(acc[3] + invM * ew0.w);
    en[4] = elu(acc[4] + invM * ew1.x); en[5] = elu(acc[5] + invM * ew1.y);
    en[6] = elu(acc[6] + invM * ew1.z); en[7] = elu(acc[7] + invM * ew1.w);

    // scatter: xacc[i][d] += w_edge(k,i) * Enew[k][d]
#pragma unroll
    for (int t = 0; t < 4; t++) {
        if (iv[t] >= 0) {
            float* dst = &g_xacc[iv[t] * DHH];
            float w = e2v[t] * invColS;
#pragma unroll
            for (int d = 0; d < DHH; d++) atomicAdd(dst + d, w * en[d]);
        }
    }
}

// ---------------- K4: epilogue (2 elems/thread) + cleanup --------------------
__global__ void k_out(float* __restrict__ out) {
    pdl_wait();
    pdl_trigger();     // EARLY: next replay's k_main prelaunches + starts H loads
    const int HALF = NN * DHH / 2;                     // 32768
    int gid = blockIdx.x * blockDim.x + threadIdx.x;   // HALF threads
    int g2 = gid + HALF;
    const float invN = 1.f / NN;
    float xa0 = g_xacc[gid];
    float xa1 = g_xacc[g2];
    float en0 = g_empty_en[gid & 7];
    float en1 = g_empty_en[g2 & 7];
    out[gid] = elu(xa0 + invN * en0);
    out[g2]  = elu(xa1 + invN * en1);
    // ---- restore zero-invariants for next replay ----
    g_xacc[gid] = 0.f;
    g_xacc[g2]  = 0.f;
    if (gid < NN) g_row_cnt[gid] = 0;
    if (gid < MM) g_col_cnt[gid] = 0;
}

// -----------------------------------------------------------------------------
extern "C" void kernel_launch(void* const* d_in, const int* in_sizes, int n_in,
                              void* d_out, int out_size) {
    const float* X  = (const float*)d_in[0];
    const float* E  = (const float*)d_in[1];
    const float* H  = (const float*)d_in[2];
    const float* W  = (const float*)d_in[3];
    const float* ax = (const float*)d_in[4];
    const float* ae = (const float*)d_in[5];
    float* out = (float*)d_out;

    cudaLaunchAttribute attr;
    attr.id = cudaLaunchAttributeProgrammaticStreamSerialization;
    attr.val.programmaticStreamSerializationAllowed = 1;

    cudaLaunchConfig_t cfg = {};
    cfg.blockDim = dim3(256);
    cfg.dynamicSmemBytes = 0;
    cfg.stream = 0;
    cfg.attrs = &attr;
    cfg.numAttrs = 1;

    cfg.gridDim = dim3(PROJ_BLOCKS + SCAN_BLOCKS);
    cudaLaunchKernelEx(&cfg, k_main, X, E, H, W, ax, ae);

    cfg.gridDim = dim3(NN * 8 / 256);
    cudaLaunchKernelEx(&cfg, k_stats);

    cfg.gridDim = dim3(MM * 32 / 256);
    cudaLaunchKernelEx(&cfg, k_enew);

    cfg.gridDim = dim3(NN * DHH / 2 / 256);
    cudaLaunchKernelEx(&cfg, k_out, out);
}

// round 13
// speedup vs baseline: 1.8441x; 1.0616x over previous
#include <cuda_runtime.h>

#define NN 8192
#define MM 2048
#define DD 256
#define DHH 8
#define ROW_CAP 64
#define COL_CAP 128
#define PROJ_BLOCKS 40          // (NN+MM)/256
#define SCAN_BLOCKS 2048
#define SCAN_ITERS 8            // NN*MM/4 / (SCAN_BLOCKS*256)

// ---------------- scratch (static device globals; zero-init at load) ---------
__device__ float g_sx[NN];
__device__ float g_s2[NN];
__device__ float g_se[MM];
__device__ float g_s1[MM];
__device__ int   g_row_cnt[NN];        // zero at entry; re-zeroed in k_out
__device__ int   g_col_cnt[MM];
__device__ __align__(16) int g_row_edges[NN * ROW_CAP];
__device__ int   g_col_nodes[MM * COL_CAP];
// packed per-node record: [sx, 1/rowSum, s2, 0, WX0..7, pad4] (stride 16 floats)
__device__ __align__(16) float g_npack[NN * 16];
__device__ __align__(16) float g_empty_wx[DHH];     // zeroed by proj each replay
__device__ __align__(16) float g_empty_en[DHH];
__device__ __align__(16) float g_xacc[NN * DHH];    // zero at entry; re-zeroed in k_out

__device__ __forceinline__ float leaky(float x) { return x >= 0.f ? x : 0.2f * x; }
// fast ELU: __expf(x)-1 (~6e-8 abs err vs expm1f; global tol is 1e-3)
__device__ __forceinline__ float elu(float x)   { return x > 0.f ? x : __expf(x) - 1.f; }
__device__ __forceinline__ void pdl_wait()    { asm volatile("griddepcontrol.wait;" ::: "memory"); }
__device__ __forceinline__ void pdl_trigger() { asm volatile("griddepcontrol.launch_dependents;" ::: "memory"); }
// vector reduction: 4 floats, one L2 atomic op (sm_90+)
__device__ __forceinline__ void red_add_v4(float* p, float a, float b, float c, float d) {
    asm volatile("red.global.add.v4.f32 [%0], {%1, %2, %3, %4};"
                 :: "l"(p), "f"(a), "f"(b), "f"(c), "f"(d) : "memory");
}

// ---------------- K1: fused projection + H scan (independent block groups) ---
// Pre-wait: input-only loads/compute (safe vs prior replay).
// Post-wait: persistent-state writes. Trigger AFTER all writes.
__global__ void k_main(const float* __restrict__ X, const float* __restrict__ E,
                       const float* __restrict__ H, const float* __restrict__ W,
                       const float* __restrict__ ax, const float* __restrict__ ae) {
    if (blockIdx.x >= PROJ_BLOCKS) {
        // ---- scan: H loads PRE-wait (input-only), atomics POST-wait ----
        int t = (blockIdx.x - PROJ_BLOCKS) * blockDim.x + threadIdx.x;
        const int stride = SCAN_BLOCKS * 256;
        const uint4* H4 = reinterpret_cast<const uint4*>(H);
        uint4 v[SCAN_ITERS];
#pragma unroll
        for (int it = 0; it < SCAN_ITERS; it++) v[it] = H4[t + it * stride];

        pdl_wait();        // prior replay's k_out re-zeroed counters

#pragma unroll
        for (int it = 0; it < SCAN_ITERS; it++) {
            uint4 h = v[it];
            if (h.x | h.y | h.z | h.w) {
                int base = (t + it * stride) * 4;
                unsigned c4[4] = {h.x, h.y, h.z, h.w};
#pragma unroll
                for (int c = 0; c < 4; c++) {
                    if (c4[c]) {
                        int lin = base + c;
                        int i = lin >> 11;        // / MM
                        int k = lin & (MM - 1);   // % MM
                        int p = atomicAdd(&g_row_cnt[i], 1);
                        if (p < ROW_CAP) g_row_edges[i * ROW_CAP + p] = k;
                        int q = atomicAdd(&g_col_cnt[k], 1);
                        if (q < COL_CAP) g_col_nodes[k * COL_CAP + q] = i;
                    }
                }
            }
        }
        pdl_trigger();     // publishes complete lists/counts
        return;
    }

    // ---- projection: full compute PRE-wait (inputs only) ----
    __shared__ float sW[DD * DHH];
    __shared__ float sax[2 * DHH], sae[2 * DHH];
    for (int j = threadIdx.x; j < DD * DHH; j += blockDim.x) sW[j] = W[j];
    if (threadIdx.x < 2 * DHH) {
        sax[threadIdx.x] = ax[threadIdx.x];
        sae[threadIdx.x] = ae[threadIdx.x];
    }
    __syncthreads();

    int r = blockIdx.x * blockDim.x + threadIdx.x;   // 0..10239
    const float* src = (r < NN) ? (X + (size_t)r * DD)
                                : (E + (size_t)(r - NN) * DD);
    float acc[DHH];
#pragma unroll
    for (int d = 0; d < DHH; d++) acc[d] = 0.f;

    const float4* Ar = reinterpret_cast<const float4*>(src);
#pragma unroll 4
    for (int j4 = 0; j4 < DD / 4; j4++) {
        float4 x = Ar[j4];
        int j = 4 * j4;
#pragma unroll
        for (int d = 0; d < DHH; d++) acc[d] += x.x * sW[(j + 0) * DHH + d];
#pragma unroll
        for (int d = 0; d < DHH; d++) acc[d] += x.y * sW[(j + 1) * DHH + d];
#pragma unroll
        for (int d = 0; d < DHH; d++) acc[d] += x.z * sW[(j + 2) * DHH + d];
#pragma unroll
        for (int d = 0; d < DHH; d++) acc[d] += x.w * sW[(j + 3) * DHH + d];
    }
    float d1 = 0.f, d2 = 0.f;
    if (r < NN) {
#pragma unroll
        for (int d = 0; d < DHH; d++) {
            d1 += acc[d] * sax[d];          // alpha_x[:dh]
            d2 += acc[d] * sae[DHH + d];    // alpha_e[dh:]
        }
    } else {
#pragma unroll
        for (int d = 0; d < DHH; d++) {
            d1 += acc[d] * sax[DHH + d];    // alpha_x[dh:]
            d2 += acc[d] * sae[d];          // alpha_e[:dh]
        }
    }

    pdl_wait();        // prior replay fully done -> safe to overwrite state

    if (r < DHH) { g_empty_wx[r] = 0.f; g_empty_en[r] = 0.f; }
    if (r < NN) {
        g_sx[r] = d1; g_s2[r] = d2;
        float4* np = reinterpret_cast<float4*>(&g_npack[r * 16]);
        np[0] = make_float4(d1, 0.f, d2, 0.f);
        np[1] = make_float4(acc[0], acc[1], acc[2], acc[3]);
        np[2] = make_float4(acc[4], acc[5], acc[6], acc[7]);
    } else {
        int k = r - NN;
        g_se[k] = d1; g_s1[k] = d2;
    }
    pdl_trigger();     // publishes proj outputs
}

// ---------------- K2: row exp-sums (8 lanes/node) + empty detection ----------
__global__ void k_stats() {
    pdl_wait();
    int gid = blockIdx.x * blockDim.x + threadIdx.x;   // NN*8 threads
    int i = gid >> 3, l8 = gid & 7;
    int cnt = min(g_row_cnt[i], ROW_CAP);
    if (cnt == 0) {
        if (l8 == 0) {
            const float4* w = reinterpret_cast<const float4*>(&g_npack[i * 16 + 4]);
            float4 w0 = w[0], w1 = w[1];
            red_add_v4(&g_empty_wx[0], w0.x, w0.y, w0.z, w0.w);
            red_add_v4(&g_empty_wx[4], w1.x, w1.y, w1.z, w1.w);
        }
    } else {
        float sxi = g_sx[i];
        float s = 0.f;
        for (int j = l8; j < cnt; j += 8)
            s += __expf(leaky(sxi + g_se[g_row_edges[i * ROW_CAP + j]]));
        s += __shfl_xor_sync(0xffffffffu, s, 4);
        s += __shfl_xor_sync(0xffffffffu, s, 2);
        s += __shfl_xor_sync(0xffffffffu, s, 1);
        if (l8 == 0) g_npack[i * 16 + 1] = 1.f / s;
    }
    pdl_trigger();     // publishes rowSums + empty_wx
}

// ---------------- K3: E_new + col softmax + scatter --------------------------
// Pre-wait: only k_main-sourced data (lists, sx/s2/WX, se/s1) -- final by
// stream order since k_stats launched after k_main completed.
// Post-wait: 1/rowSum + empty_wx reads, reductions, scatter.
__global__ void __launch_bounds__(256) k_enew() {
    int gid = blockIdx.x * blockDim.x + threadIdx.x;
    int k = gid >> 5;                                 // exactly MM warps
    int lane = gid & 31;
    // ---- pre-wait ----
    int cnt = min(g_col_cnt[k], COL_CAP);
    float sek = g_se[k], s1k = g_s1[k];

    int   iv[4];
    float e1v[4], e2v[4];
    float wx[4][DHH];
    float colS = 0.f;
#pragma unroll
    for (int t = 0; t < 4; t++) {
        int j = lane + 32 * t;
        bool act = (j < cnt);
        int i = act ? g_col_nodes[k * COL_CAP + j] : 0;
        iv[t] = act ? i : -1;
        const float4* np = reinterpret_cast<const float4*>(&g_npack[i * 16]);
        float4 p0 = np[0];                 // x=sx, z=s2 valid; y possibly stale
        float4 p1 = np[1], p2 = np[2];
        float e1 = act ? __expf(leaky(p0.x + sek)) : 0.f;
        float e2 = act ? __expf(leaky(s1k + p0.z)) : 0.f;
        e1v[t] = e1; e2v[t] = e2; colS += e2;
        wx[t][0] = p1.x; wx[t][1] = p1.y; wx[t][2] = p1.z; wx[t][3] = p1.w;
        wx[t][4] = p2.x; wx[t][5] = p2.y; wx[t][6] = p2.z; wx[t][7] = p2.w;
    }
#pragma unroll
    for (int off = 16; off > 0; off >>= 1)
        colS += __shfl_xor_sync(0xffffffffu, colS, off);

    pdl_wait();        // k_stats done: 1/rowSum + empty_wx final

    const float invM = 1.f / MM;
    if (cnt == 0) {
        if (lane == 0) {
            float a = elu(invM * g_empty_wx[0]), b = elu(invM * g_empty_wx[1]);
            float c = elu(invM * g_empty_wx[2]), d = elu(invM * g_empty_wx[3]);
            red_add_v4(&g_empty_en[0], a, b, c, d);
            a = elu(invM * g_empty_wx[4]); b = elu(invM * g_empty_wx[5]);
            c = elu(invM * g_empty_wx[6]); d = elu(invM * g_empty_wx[7]);
            red_add_v4(&g_empty_en[4], a, b, c, d);
        }
        pdl_trigger();
        return;
    }

    // fetch fresh 1/rowSum scalars (MLP=4)
    float inv[4];
#pragma unroll
    for (int t = 0; t < 4; t++)
        inv[t] = (iv[t] >= 0) ? g_npack[iv[t] * 16 + 1] : 0.f;

    float acc[DHH];
#pragma unroll
    for (int d = 0; d < DHH; d++) acc[d] = 0.f;
#pragma unroll
    for (int t = 0; t < 4; t++) {
        float wt = e1v[t] * inv[t];
#pragma unroll
        for (int d = 0; d < DHH; d++) acc[d] += wt * wx[t][d];
    }
#pragma unroll
    for (int d = 0; d < DHH; d++)
#pragma unroll
        for (int off = 16; off > 0; off >>= 1)
            acc[d] += __shfl_xor_sync(0xffffffffu, acc[d], off);

    float invColS = __fdividef(1.f, colS);
    float4 ew0 = *reinterpret_cast<const float4*>(&g_empty_wx[0]);
    float4 ew1 = *reinterpret_cast<const float4*>(&g_empty_wx[4]);
    float en[DHH];
    en[0] = elu(acc[0] + invM * ew0.x); en[1] = elu(acc[1] + invM * ew0.y);
    en[2] = elu(acc[2] + invM * ew0.z); en[3] = elu(acc[3] + invM * ew0.w);
    en[4] = elu(acc[4] + invM * ew1.x); en[5] = elu(acc[5] + invM * ew1.y);
    en[6] = elu(acc[6] + invM * ew1.z); en[7] = elu(acc[7] + invM * ew1.w);

    // scatter: xacc[i][0..7] += w * Enew[k][0..7]  (two v4 red ops per pair)
#pragma unroll
    for (int t = 0; t < 4; t++) {
        if (iv[t] >= 0) {
            float* dst = &g_xacc[iv[t] * DHH];
            float w = e2v[t] * invColS;
            red_add_v4(dst,     w * en[0], w * en[1], w * en[2], w * en[3]);
            red_add_v4(dst + 4, w * en[4], w * en[5], w * en[6], w * en[7]);
        }
    }
    pdl_trigger();     // publishes xacc + empty_en
}

// ---------------- K4: epilogue (2 elems/thread) + cleanup --------------------
__global__ void k_out(float* __restrict__ out) {
    pdl_wait();
    const int HALF = NN * DHH / 2;                     // 32768
    int gid = blockIdx.x * blockDim.x + threadIdx.x;   // HALF threads
    int g2 = gid + HALF;
    const float invN = 1.f / NN;
    float xa0 = g_xacc[gid];
    float xa1 = g_xacc[g2];
    float en0 = g_empty_en[gid & 7];
    float en1 = g_empty_en[g2 & 7];
    out[gid] = elu(xa0 + invN * en0);
    out[g2]  = elu(xa1 + invN * en1);
    // ---- restore zero-invariants for next replay ----
    g_xacc[gid] = 0.f;
    g_xacc[g2]  = 0.f;
    if (gid < NN) g_row_cnt[gid] = 0;
    if (gid < MM) g_col_cnt[gid] = 0;
    pdl_trigger();     // publishes re-zeroed state (next k_main waits on this)
}

// -----------------------------------------------------------------------------
extern "C" void kernel_launch(void* const* d_in, const int* in_sizes, int n_in,
                              void* d_out, int out_size) {
    const float* X  = (const float*)d_in[0];
    const float* E  = (const float*)d_in[1];
    const float* H  = (const float*)d_in[2];
    const float* W  = (const float*)d_in[3];
    const float* ax = (const float*)d_in[4];
    const float* ae = (const float*)d_in[5];
    float* out = (float*)d_out;

    cudaLaunchAttribute attr;
    attr.id = cudaLaunchAttributeProgrammaticStreamSerialization;
    attr.val.programmaticStreamSerializationAllowed = 1;

    cudaLaunchConfig_t cfg = {};
    cfg.blockDim = dim3(256);
    cfg.dynamicSmemBytes = 0;
    cfg.stream = 0;
    cfg.attrs = &attr;
    cfg.numAttrs = 1;

    cfg.gridDim = dim3(PROJ_BLOCKS + SCAN_BLOCKS);
    cudaLaunchKernelEx(&cfg, k_main, X, E, H, W, ax, ae);

    cfg.gridDim = dim3(NN * 8 / 256);
    cudaLaunchKernelEx(&cfg, k_stats);

    cfg.gridDim = dim3(MM * 32 / 256);
    cudaLaunchKernelEx(&cfg, k_enew);

    cfg.gridDim = dim3(NN * DHH / 2 / 256);
    cudaLaunchKernelEx(&cfg, k_out, out);
}